// round 16
// baseline (speedup 1.0000x reference)
#include <cuda_runtime.h>
#include <cuda_fp16.h>
#include <math.h>
#include <stdint.h>

static constexpr int PB  = 2;
static constexpr int PS  = 8192;
static constexpr int PD  = 768;
static constexpr int PH  = 12;
static constexpr int PHD = 64;
static constexpr int PW  = 256;
static constexpr int PDFF= 3072;
static constexpr int NT  = PB * PS;     // 16384
static constexpr int QS  = 3 * PD;      // 2304 fused qkv row stride

// ---------------- scratch (device globals; no allocation) ---------------------
__device__ float g_src2[NT * PD];
__device__ float g_bqkv[QS];

// fp16 activations
__device__ __half g_hf  [NT * PD];
__device__ __half g_tmpf[NT * PD];
__device__ __half g_h2f [NT * PD];
__device__ __half g_af  [NT * PD];
__device__ __half g_xf  [NT * PD];
__device__ __half g_qkv [(size_t)NT * QS];
__device__ __half g_fff [(size_t)NT * PDFF];

// weights: fp16, TRANSPOSED to [N,K]
__device__ __half g_wqkv[QS * PD];      // rows: q(scaled 1/8), k, v
__device__ __half g_wo  [PD * PD];
__device__ __half g_wi  [PDFF * PD];
__device__ __half g_wo2 [PD * PDFF];
__device__ __half g_w1  [PDFF * PD];
__device__ __half g_w2  [PD * PDFF];

// ---------------- helpers -----------------------------------------------------
__device__ __forceinline__ uint32_t smem_u32(const void* p) {
    uint32_t a;
    asm("{ .reg .u64 t; cvta.to.shared.u64 t, %1; cvt.u32.u64 %0, t; }"
        : "=r"(a) : "l"(p));
    return a;
}
__device__ __forceinline__ void cp16(uint32_t saddr, const void* gaddr) {
    asm volatile("cp.async.cg.shared.global [%0], [%1], 16;"
                 :: "r"(saddr), "l"(gaddr) : "memory");
}
#define CP_COMMIT() asm volatile("cp.async.commit_group;" ::: "memory")
#define CP_WAIT(n)  asm volatile("cp.async.wait_group %0;" :: "n"(n) : "memory")

__device__ __forceinline__ void ldsm4(uint32_t* r, uint32_t addr) {
    asm volatile("ldmatrix.sync.aligned.m8n8.x4.shared.b16 {%0,%1,%2,%3}, [%4];"
                 : "=r"(r[0]), "=r"(r[1]), "=r"(r[2]), "=r"(r[3]) : "r"(addr));
}
__device__ __forceinline__ void ldsm4t(uint32_t* r, uint32_t addr) {
    asm volatile("ldmatrix.sync.aligned.m8n8.x4.trans.shared.b16 {%0,%1,%2,%3}, [%4];"
                 : "=r"(r[0]), "=r"(r[1]), "=r"(r[2]), "=r"(r[3]) : "r"(addr));
}
__device__ __forceinline__ void mma16816(float* c, const uint32_t* a, const uint32_t* b) {
    asm volatile(
        "mma.sync.aligned.m16n8k16.row.col.f32.f16.f16.f32 "
        "{%0,%1,%2,%3}, {%4,%5,%6,%7}, {%8,%9}, {%0,%1,%2,%3};"
        : "+f"(c[0]), "+f"(c[1]), "+f"(c[2]), "+f"(c[3])
        : "r"(a[0]), "r"(a[1]), "r"(a[2]), "r"(a[3]), "r"(b[0]), "r"(b[1]));
}
// fp16-accumulator variant (rate-class experiment)
__device__ __forceinline__ void mma16816h(uint32_t* c, const uint32_t* a, const uint32_t* b) {
    asm volatile(
        "mma.sync.aligned.m16n8k16.row.col.f16.f16.f16.f16 "
        "{%0,%1}, {%2,%3,%4,%5}, {%6,%7}, {%0,%1};"
        : "+r"(c[0]), "+r"(c[1])
        : "r"(a[0]), "r"(a[1]), "r"(a[2]), "r"(a[3]), "r"(b[0]), "r"(b[1]));
}
__device__ __forceinline__ uint32_t packh2(float a, float b) {
    __half2 h = __floats2half2_rn(a, b);
    return *(uint32_t*)&h;
}

// ---------------- block reduce (sum of two values, 256 threads) ---------------
__device__ __forceinline__ void reduce2(float& a, float& b, float* sbuf) {
    int lane = threadIdx.x & 31;
    int wid  = threadIdx.x >> 5;
#pragma unroll
    for (int o = 16; o > 0; o >>= 1) {
        a += __shfl_down_sync(0xffffffffu, a, o);
        b += __shfl_down_sync(0xffffffffu, b, o);
    }
    __syncthreads();
    if (lane == 0) { sbuf[wid] = a; sbuf[8 + wid] = b; }
    __syncthreads();
    if (threadIdx.x < 32) {
        a = (lane < 8) ? sbuf[lane] : 0.f;
        b = (lane < 8) ? sbuf[8 + lane] : 0.f;
#pragma unroll
        for (int o = 4; o > 0; o >>= 1) {
            a += __shfl_down_sync(0xffffffffu, a, o);
            b += __shfl_down_sync(0xffffffffu, b, o);
        }
        if (lane == 0) { sbuf[0] = a; sbuf[8] = b; }
    }
    __syncthreads();
    a = sbuf[0]; b = sbuf[8];
}

// -------- fused qkv weight convert: 3x W[768,768] -> T[2304,768], q scaled ----
__global__ void k_wconv3(const float* __restrict__ W0, const float* __restrict__ W1,
                         const float* __restrict__ W2, __half* __restrict__ Th) {
    __shared__ float t[32][33];
    int z = blockIdx.z;
    const float* W = (z == 0) ? W0 : ((z == 1) ? W1 : W2);
    float scale = (z == 0) ? 0.125f : 1.f;
    int n0 = blockIdx.x * 32, k0 = blockIdx.y * 32;
    int tx = threadIdx.x, ty = threadIdx.y;   // 32 x 8
#pragma unroll
    for (int i = 0; i < 32; i += 8)
        t[ty + i][tx] = W[(size_t)(k0 + ty + i) * PD + n0 + tx];
    __syncthreads();
#pragma unroll
    for (int i = 0; i < 32; i += 8) {
        size_t o = (size_t)(z * PD + n0 + ty + i) * PD + k0 + tx;
        Th[o] = __float2half_rn(t[tx][ty + i] * scale);
    }
}

__global__ void k_bias3(const float* __restrict__ bq, const float* __restrict__ bk,
                        const float* __restrict__ bv, float* __restrict__ o) {
    int i = blockIdx.x * 256 + threadIdx.x;
    if (i < PD) o[i] = bq[i] * 0.125f;
    else if (i < 2 * PD) o[i] = bk[i - PD];
    else if (i < QS) o[i] = bv[i - 2 * PD];
}

// -------- weight convert + transpose: W[K,N] fp32 -> T[N,K] fp16 --------------
__global__ void k_wconv(const float* __restrict__ W, __half* __restrict__ Th,
                        int K, int N) {
    __shared__ float t[32][33];
    int n0 = blockIdx.x * 32, k0 = blockIdx.y * 32;
    int tx = threadIdx.x, ty = threadIdx.y;
#pragma unroll
    for (int i = 0; i < 32; i += 8)
        t[ty + i][tx] = W[(size_t)(k0 + ty + i) * N + n0 + tx];
    __syncthreads();
#pragma unroll
    for (int i = 0; i < 32; i += 8) {
        size_t o = (size_t)(n0 + ty + i) * K + k0 + tx;
        Th[o] = __float2half_rn(t[tx][ty + i]);
    }
}

// -------- K1: double LN + pos/tt; writes h fp16 only --------------------------
__global__ void k_embed(const float* __restrict__ src, const float* __restrict__ pos,
                        const float* __restrict__ tt,
                        const float* __restrict__ n1s, const float* __restrict__ n1b,
                        const float* __restrict__ es,  const float* __restrict__ eb,
                        __half* __restrict__ oh) {
    __shared__ float sbuf[16];
    int row = blockIdx.x;
    int s   = row % PS;
    const float* x = src + (size_t)row * PD;
    int t = threadIdx.x;
    float v0 = x[t], v1 = x[t + 256], v2 = x[t + 512];
    float sum = v0 + v1 + v2, sq = v0*v0 + v1*v1 + v2*v2;
    reduce2(sum, sq, sbuf);
    float m = sum / PD;
    float r = rsqrtf(sq / PD - m * m + 1e-5f);
    const float* ps = pos + (size_t)s * PD;
    float y0 = (v0 - m) * r * n1s[t]       + n1b[t]       + ps[t]       + tt[t];
    float y1 = (v1 - m) * r * n1s[t + 256] + n1b[t + 256] + ps[t + 256] + tt[t + 256];
    float y2 = (v2 - m) * r * n1s[t + 512] + n1b[t + 512] + ps[t + 512] + tt[t + 512];
    sum = y0 + y1 + y2; sq = y0*y0 + y1*y1 + y2*y2;
    reduce2(sum, sq, sbuf);
    m = sum / PD;
    r = rsqrtf(sq / PD - m * m + 1e-12f);
    size_t base = (size_t)row * PD;
    oh[base + t]       = __float2half_rn((y0 - m) * r * es[t]       + eb[t]);
    oh[base + t + 256] = __float2half_rn((y1 - m) * r * es[t + 256] + eb[t + 256]);
    oh[base + t + 512] = __float2half_rn((y2 - m) * r * es[t + 512] + eb[t + 512]);
}

// -------- out = ln(a + b) with fp16 inputs; writes fp16 -----------------------
__global__ void k_add_ln(const __half* __restrict__ a, const __half* __restrict__ b,
                         const float* __restrict__ sc, const float* __restrict__ bv,
                         float eps, __half* __restrict__ oh) {
    __shared__ float sbuf[16];
    int row = blockIdx.x;
    int t = threadIdx.x;
    size_t base = (size_t)row * PD;
    float y0 = __half2float(a[base + t])       + __half2float(b[base + t]);
    float y1 = __half2float(a[base + t + 256]) + __half2float(b[base + t + 256]);
    float y2 = __half2float(a[base + t + 512]) + __half2float(b[base + t + 512]);
    float sum = y0 + y1 + y2, sq = y0*y0 + y1*y1 + y2*y2;
    reduce2(sum, sq, sbuf);
    float m = sum / PD;
    float r = rsqrtf(sq / PD - m * m + eps);
    oh[base + t]       = __float2half_rn((y0 - m) * r * sc[t]       + bv[t]);
    oh[base + t + 256] = __float2half_rn((y1 - m) * r * sc[t + 256] + bv[t + 256]);
    oh[base + t + 512] = __float2half_rn((y2 - m) * r * sc[t + 512] + bv[t + 512]);
}

// -------- out-LN -> src2 (fp32) -> n2-LN -> x (fp16); fp16 inputs -------------
__global__ void k_mid(const __half* __restrict__ h2, const __half* __restrict__ tp,
                      const float* __restrict__ os, const float* __restrict__ ob,
                      const float* __restrict__ src,
                      const float* __restrict__ n2s, const float* __restrict__ n2b,
                      float* __restrict__ src2, __half* __restrict__ xh) {
    __shared__ float sbuf[16];
    int row = blockIdx.x;
    int t = threadIdx.x;
    size_t base = (size_t)row * PD;
    float y0 = __half2float(h2[base + t])       + __half2float(tp[base + t]);
    float y1 = __half2float(h2[base + t + 256]) + __half2float(tp[base + t + 256]);
    float y2 = __half2float(h2[base + t + 512]) + __half2float(tp[base + t + 512]);
    float sum = y0 + y1 + y2, sq = y0*y0 + y1*y1 + y2*y2;
    reduce2(sum, sq, sbuf);
    float m = sum / PD;
    float r = rsqrtf(sq / PD - m * m + 1e-12f);
    const float* sp = src + base;
    float s0 = sp[t]       + (y0 - m) * r * os[t]       + ob[t];
    float s1 = sp[t + 256] + (y1 - m) * r * os[t + 256] + ob[t + 256];
    float s2 = sp[t + 512] + (y2 - m) * r * os[t + 512] + ob[t + 512];
    src2[base + t] = s0; src2[base + t + 256] = s1; src2[base + t + 512] = s2;
    sum = s0 + s1 + s2; sq = s0*s0 + s1*s1 + s2*s2;
    reduce2(sum, sq, sbuf);
    m = sum / PD;
    r = rsqrtf(sq / PD - m * m + 1e-5f);
    xh[base + t]       = __float2half_rn((s0 - m) * r * n2s[t]       + n2b[t]);
    xh[base + t + 256] = __float2half_rn((s1 - m) * r * n2s[t + 256] + n2b[t + 256]);
    xh[base + t + 512] = __float2half_rn((s2 - m) * r * n2s[t + 512] + n2b[t + 512]);
}

// ---------------- HMMA GEMM, fp16-accumulator experiment ----------------------
// Tile 128x128x64, 8 warps (2m x 4n), warp tile 64x32, 256 threads, 1 CTA/SM.
// Accumulate 2 K-chunks (K=128) in fp16 C-fragments, promote to fp32, clear.
static constexpr int LDT   = 72;
static constexpr int ABYTES= 128 * LDT * 2;     // 18432 per array
static constexpr int STAGE = 2 * ABYTES;        // 36864 (A, B)
static constexpr int NSTG  = 3;
static constexpr int GSMEM = NSTG * STAGE;      // 110592

template<int MODE, bool WF32, bool WH, bool HASRES>
__global__ void __launch_bounds__(256, 1)
k_mma_gemm(const __half* __restrict__ A, const __half* __restrict__ B,
           const float* __restrict__ bias, const float* __restrict__ res,
           float* __restrict__ Cf, __half* __restrict__ Chh,
           int M, int N, int K) {
    extern __shared__ char smem[];
    uint32_t sbase = smem_u32(smem);
    int tid  = threadIdx.x;
    int wid  = tid >> 5, lane = tid & 31;
    int wm   = (wid >> 2) * 64;     // warp m offset (0 / 64)
    int wn   = (wid & 3) * 32;      // warp n offset

    int m0 = blockIdx.y * 128, n0 = blockIdx.x * 128;
    int nK = K >> 6;

    const __half* pa = A + (size_t)m0 * K;
    const __half* pb = B + (size_t)n0 * K;

    float facc[4][4][4];
    uint32_t hc[4][4][2];
#pragma unroll
    for (int a = 0; a < 4; a++)
#pragma unroll
        for (int b = 0; b < 4; b++) {
#pragma unroll
            for (int c = 0; c < 4; c++) facc[a][b][c] = 0.f;
            hc[a][b][0] = 0u; hc[a][b][1] = 0u;
        }

    int lrow = tid >> 3;            // base row (0..31), +32*i
    int lseg = tid & 7;

    auto load_stage = [&](int kc, int s) {
        uint32_t st = sbase + s * STAGE;
        size_t ko = (size_t)(kc << 6) + (size_t)lseg * 8;
#pragma unroll
        for (int i = 0; i < 4; i++) {
            int r = lrow + i * 32;
            uint32_t so = (uint32_t)r * (LDT * 2) + (uint32_t)lseg * 16;
            size_t go = (size_t)r * K + ko;
            cp16(st + so,          pa + go);
            cp16(st + ABYTES + so, pb + go);
        }
    };

    load_stage(0, 0); CP_COMMIT();
    load_stage(1, 1); CP_COMMIT();

    int a_r  = lane & 15;
    int a_k8 = (lane >> 4) * 8;
    int b4_r = ((lane >> 4) & 1) * 8 + (lane & 7);
    int b4_k8= ((lane >> 3) & 1) * 8;

    for (int kc = 0; kc < nK; kc++) {
        int s = kc % NSTG;
        if (kc + 1 < nK) { CP_WAIT(1); } else { CP_WAIT(0); }
        __syncthreads();
        if (kc + 2 < nK) { load_stage(kc + 2, (kc + 2) % NSTG); CP_COMMIT(); }

        uint32_t sA = sbase + s * STAGE;
        uint32_t sB = sA + ABYTES;
#pragma unroll
        for (int ks = 0; ks < 4; ks++) {
            uint32_t ah[4][4], bf[2][4];
#pragma unroll
            for (int mi = 0; mi < 4; mi++) {
                uint32_t off = ((uint32_t)(wm + mi * 16 + a_r) * LDT +
                                (uint32_t)(ks * 16 + a_k8)) * 2;
                ldsm4(ah[mi], sA + off);
            }
#pragma unroll
            for (int p = 0; p < 2; p++) {
                uint32_t off = ((uint32_t)(wn + p * 16 + b4_r) * LDT +
                                (uint32_t)(ks * 16 + b4_k8)) * 2;
                ldsm4(bf[p], sB + off);
            }
#pragma unroll
            for (int mi = 0; mi < 4; mi++)
#pragma unroll
                for (int p = 0; p < 2; p++) {
                    mma16816h(hc[mi][2 * p],     ah[mi], &bf[p][0]);
                    mma16816h(hc[mi][2 * p + 1], ah[mi], &bf[p][2]);
                }
        }
        // promote fp16 partials to fp32 every 2 chunks (and at end)
        if ((kc & 1) || kc == nK - 1) {
#pragma unroll
            for (int mi = 0; mi < 4; mi++)
#pragma unroll
                for (int ni = 0; ni < 4; ni++) {
                    float2 f0 = __half22float2(*(__half2*)&hc[mi][ni][0]);
                    float2 f1 = __half22float2(*(__half2*)&hc[mi][ni][1]);
                    facc[mi][ni][0] += f0.x; facc[mi][ni][1] += f0.y;
                    facc[mi][ni][2] += f1.x; facc[mi][ni][3] += f1.y;
                    hc[mi][ni][0] = 0u; hc[mi][ni][1] = 0u;
                }
        }
        __syncthreads();
    }

    auto epi = [&](float v0, float v1, int m, int n) {
        float2 bb = *(const float2*)(bias + n);
        float o0 = v0 + bb.x;
        float o1 = v1 + bb.y;
        if (MODE == 1) { o0 = fmaxf(o0, 0.f); o1 = fmaxf(o1, 0.f); }
        if (MODE == 2) {
            o0 = 0.5f * o0 * (1.f + erff(o0 * 0.7071067811865476f));
            o1 = 0.5f * o1 * (1.f + erff(o1 * 0.7071067811865476f));
        }
        size_t off = (size_t)m * N + n;
        if (HASRES) {
            float2 rr = *(const float2*)(res + off);
            o0 += rr.x; o1 += rr.y;
        }
        if (WF32) {
            float2 ov = { o0, o1 };
            *(float2*)(Cf + off) = ov;
        }
        if (WH) {
            __half2 hv; hv.x = __float2half_rn(o0); hv.y = __float2half_rn(o1);
            *(__half2*)(Chh + off) = hv;
        }
    };
    int mrow = lane >> 2;
    int ncol = (lane & 3) * 2;
#pragma unroll
    for (int mi = 0; mi < 4; mi++)
#pragma unroll
        for (int ni = 0; ni < 4; ni++) {
            int m = m0 + wm + mi * 16 + mrow;
            int n = n0 + wn + ni * 8 + ncol;
            epi(facc[mi][ni][0], facc[mi][ni][1], m,     n);
            epi(facc[mi][ni][2], facc[mi][ni][3], m + 8, n);
        }
}

// ---------------- tensor-core banded flash attention (64-query blocks) --------
static constexpr int LDA   = 72;                // halves
static constexpr int ATILE = 64 * LDA;          // halves per tile
static constexpr int ASMEM = (5 * ATILE) * 2;   // Q + 2 stages * (K,V) = 46080 B

__global__ void __launch_bounds__(128)
k_attn_tc(const __half* __restrict__ QKV, __half* __restrict__ Og) {
    extern __shared__ __half sa[];
    uint32_t sbQ  = smem_u32(sa);
    uint32_t sbKV = sbQ + ATILE * 2;

    int tid = threadIdx.x, wid = tid >> 5, lane = tid & 31;
    int wm = wid * 16;
    int qc = blockIdx.x, bh = blockIdx.y;
    int b = bh / PH, hh = bh % PH;
    int qbase = qc * 64;
    size_t tokq = (size_t)b * PS + qbase;
    const __half* qsrc = QKV + tokq * QS + hh * PHD;

#pragma unroll
    for (int i = 0; i < 4; i++) {
        int idx = tid + i * 128;
        int row = idx >> 3, seg = idx & 7;
        cp16(sbQ + (uint32_t)(row * LDA + seg * 8) * 2,
             qsrc + (size_t)row * QS + seg * 8);
    }

    int t0 = qbase >= 256 ? 0 : (256 - qbase) / 64;
    int t1 = (PS + 192 - qbase) / 64; if (t1 > 8) t1 = 8;

    auto stage_kv = [&](int t, int s) {
        int tb = qbase - 256 + t * 64;
        size_t tok = (size_t)b * PS + tb;
        const __half* ks = QKV + tok * QS + PD + hh * PHD;
        const __half* vs = QKV + tok * QS + 2 * PD + hh * PHD;
        uint32_t dstK = sbKV + (uint32_t)(s * 2 * ATILE) * 2;
        uint32_t dstV = dstK + ATILE * 2;
#pragma unroll
        for (int i = 0; i < 4; i++) {
            int idx = tid + i * 128;
            int row = idx >> 3, seg = idx & 7;
            uint32_t so = (uint32_t)(row * LDA + seg * 8) * 2;
            size_t go = (size_t)row * QS + seg * 8;
            cp16(dstK + so, ks + go);
            cp16(dstV + so, vs + go);
        }
    };

    stage_kv(t0, 0);
    CP_COMMIT();

    uint32_t qf[4][4];
    float O[8][4];
#pragma unroll
    for (int i = 0; i < 8; i++)
#pragma unroll
        for (int j = 0; j < 4; j++) O[i][j] = 0.f;
    float m0 = -1e30f, m1 = -1e30f, l0 = 0.f, l1 = 0.f;

    int a_r = lane & 15, a_k8 = (lane >> 4) * 8;
    int kn_r = (lane >> 4) * 8 + (lane & 7);
    int kn_c = ((lane >> 3) & 1) * 8;
    int v_r  = ((lane >> 3) & 1) * 8 + (lane & 7);
    int v_c  = (lane >> 4) * 8;

    for (int t = t0; t <= t1; t++) {
        int s = (t - t0) & 1;
        if (t < t1) { stage_kv(t + 1, s ^ 1); CP_COMMIT(); CP_WAIT(1); }
        else CP_WAIT(0);
        __syncthreads();
        if (t == t0) {
#pragma unroll
            for (int kk = 0; kk < 4; kk++)
                ldsm4(qf[kk], sbQ + (uint32_t)((wm + a_r) * LDA + kk * 16 + a_k8) * 2);
        }
        uint32_t sK = sbKV + (uint32_t)(s * 2 * ATILE) * 2;
        uint32_t sV = sK + ATILE * 2;

        float S[8][4];
#pragma unroll
        for (int i = 0; i < 8; i++)
#pragma unroll
            for (int j = 0; j < 4; j++) S[i][j] = 0.f;
#pragma unroll
        for (int np = 0; np < 4; np++) {
#pragma unroll
            for (int kk = 0; kk < 4; kk++) {
                uint32_t kf[4];
                ldsm4(kf, sK + (uint32_t)((np * 16 + kn_r) * LDA + kk * 16 + kn_c) * 2);
                mma16816(S[2 * np],     qf[kk], kf);
                mma16816(S[2 * np + 1], qf[kk], kf + 2);
            }
        }

        if (t == 0) {
            int i0 = wm + (lane >> 2);
#pragma unroll
            for (int ni = 0; ni < 8; ni++) {
                int j0 = ni * 8 + (lane & 3) * 2;
                if (j0     < i0)     S[ni][0] = -1e30f;
                if (j0 + 1 < i0)     S[ni][1] = -1e30f;
                if (j0     < i0 + 8) S[ni][2] = -1e30f;
                if (j0 + 1 < i0 + 8) S[ni][3] = -1e30f;
            }
        } else if (t == 8) {
            int i0 = wm + (lane >> 2);
#pragma unroll
            for (int ni = 0; ni < 8; ni++) {
                int j0 = ni * 8 + (lane & 3) * 2;
                if (j0     > i0)     S[ni][0] = -1e30f;
                if (j0 + 1 > i0)     S[ni][1] = -1e30f;
                if (j0     > i0 + 8) S[ni][2] = -1e30f;
                if (j0 + 1 > i0 + 8) S[ni][3] = -1e30f;
            }
        }

        float mx0 = -1e30f, mx1 = -1e30f;
#pragma unroll
        for (int ni = 0; ni < 8; ni++) {
            mx0 = fmaxf(mx0, fmaxf(S[ni][0], S[ni][1]));
            mx1 = fmaxf(mx1, fmaxf(S[ni][2], S[ni][3]));
        }
        mx0 = fmaxf(mx0, __shfl_xor_sync(0xffffffffu, mx0, 1));
        mx0 = fmaxf(mx0, __shfl_xor_sync(0xffffffffu, mx0, 2));
        mx1 = fmaxf(mx1, __shfl_xor_sync(0xffffffffu, mx1, 1));
        mx1 = fmaxf(mx1, __shfl_xor_sync(0xffffffffu, mx1, 2));
        float mn0 = fmaxf(m0, mx0), mn1 = fmaxf(m1, mx1);
        float c0 = __expf(m0 - mn0), c1 = __expf(m1 - mn1);
        float rs0 = 0.f, rs1 = 0.f;
#pragma unroll
        for (int ni = 0; ni < 8; ni++) {
            S[ni][0] = __expf(S[ni][0] - mn0);
            S[ni][1] = __expf(S[ni][1] - mn0);
            S[ni][2] = __expf(S[ni][2] - mn1);
            S[ni][3] = __expf(S[ni][3] - mn1);
            rs0 += S[ni][0] + S[ni][1];
            rs1 += S[ni][2] + S[ni][3];
        }
        rs0 += __shfl_xor_sync(0xffffffffu, rs0, 1);
        rs0 += __shfl_xor_sync(0xffffffffu, rs0, 2);
        rs1 += __shfl_xor_sync(0xffffffffu, rs1, 1);
        rs1 += __shfl_xor_sync(0xffffffffu, rs1, 2);
        l0 = l0 * c0 + rs0;
        l1 = l1 * c1 + rs1;
        m0 = mn0; m1 = mn1;
#pragma unroll
        for (int ni = 0; ni < 8; ni++) {
            O[ni][0] *= c0; O[ni][1] *= c0;
            O[ni][2] *= c1; O[ni][3] *= c1;
        }

        uint32_t ap[4][4];
#pragma unroll
        for (int kk = 0; kk < 4; kk++) {
            ap[kk][0] = packh2(S[2 * kk][0],     S[2 * kk][1]);
            ap[kk][1] = packh2(S[2 * kk][2],     S[2 * kk][3]);
            ap[kk][2] = packh2(S[2 * kk + 1][0], S[2 * kk + 1][1]);
            ap[kk][3] = packh2(S[2 * kk + 1][2], S[2 * kk + 1][3]);
        }
#pragma unroll
        for (int np = 0; np < 4; np++) {
#pragma unroll
            for (int kk = 0; kk < 4; kk++) {
                uint32_t vf[4];
                ldsm4t(vf, sV + (uint32_t)((kk * 16 + v_r) * LDA + np * 16 + v_c) * 2);
                mma16816(O[2 * np],     ap[kk], vf);
                mma16816(O[2 * np + 1], ap[kk], vf + 2);
            }
        }
        __syncthreads();
    }

    float inv0 = 1.f / l0, inv1 = 1.f / l1;
    int i0 = wm + (lane >> 2);
    size_t rb0 = (tokq + i0) * PD + hh * PHD;
    size_t rb1 = (tokq + i0 + 8) * PD + hh * PHD;
#pragma unroll
    for (int ni = 0; ni < 8; ni++) {
        int j0 = ni * 8 + (lane & 3) * 2;
        __half2 h0 = __floats2half2_rn(O[ni][0] * inv0, O[ni][1] * inv0);
        __half2 h1 = __floats2half2_rn(O[ni][2] * inv1, O[ni][3] * inv1);
        *(__half2*)(Og + rb0 + j0) = h0;
        *(__half2*)(Og + rb1 + j0) = h1;
    }
}

// ------------------------------- launch ---------------------------------------
extern "C" void kernel_launch(void* const* d_in, const int* in_sizes, int n_in,
                              void* d_out, int out_size) {
    const float* src   = (const float*)d_in[0];
    const float* pos   = (const float*)d_in[1];
    const float* tt    = (const float*)d_in[2];
    const float* embs  = (const float*)d_in[3];
    const float* embb  = (const float*)d_in[4];
    const float* wq    = (const float*)d_in[5];
    const float* bq    = (const float*)d_in[6];
    const float* wk    = (const float*)d_in[7];
    const float* bk    = (const float*)d_in[8];
    const float* wv    = (const float*)d_in[9];
    const float* bv    = (const float*)d_in[10];
    const float* wo    = (const float*)d_in[11];
    const float* bo    = (const float*)d_in[12];
    const float* atts  = (const float*)d_in[13];
    const float* attb  = (const float*)d_in[14];
    const float* wi    = (const float*)d_in[15];
    const float* bi    = (const float*)d_in[16];
    const float* wo2   = (const float*)d_in[17];
    const float* bo2   = (const float*)d_in[18];
    const float* outs  = (const float*)d_in[19];
    const float* outb  = (const float*)d_in[20];
    const float* n1s   = (const float*)d_in[21];
    const float* n1b   = (const float*)d_in[22];
    const float* n2s   = (const float*)d_in[23];
    const float* n2b   = (const float*)d_in[24];
    const float* w1    = (const float*)d_in[25];
    const float* b1    = (const float*)d_in[26];
    const float* w2    = (const float*)d_in[27];
    const float* b2    = (const float*)d_in[28];
    float* out = (float*)d_out;

    float *p_src2, *pbqkv;
    cudaGetSymbolAddress((void**)&p_src2, g_src2);
    cudaGetSymbolAddress((void**)&pbqkv,  g_bqkv);

    __half *hf, *tmpf, *h2f, *af, *xf, *fff, *qkvf;
    cudaGetSymbolAddress((void**)&hf,   g_hf);
    cudaGetSymbolAddress((void**)&tmpf, g_tmpf);
    cudaGetSymbolAddress((void**)&h2f,  g_h2f);
    cudaGetSymbolAddress((void**)&af,   g_af);
    cudaGetSymbolAddress((void**)&xf,   g_xf);
    cudaGetSymbolAddress((void**)&fff,  g_fff);
    cudaGetSymbolAddress((void**)&qkvf, g_qkv);

    __half *pwqkv, *pwo, *pwi, *pwo2, *pw1, *pw2;
    cudaGetSymbolAddress((void**)&pwqkv, g_wqkv);
    cudaGetSymbolAddress((void**)&pwo,   g_wo);
    cudaGetSymbolAddress((void**)&pwi,   g_wi);
    cudaGetSymbolAddress((void**)&pwo2,  g_wo2);
    cudaGetSymbolAddress((void**)&pw1,   g_w1);
    cudaGetSymbolAddress((void**)&pw2,   g_w2);

    cudaFuncSetAttribute(k_mma_gemm<0,false,true,false>, cudaFuncAttributeMaxDynamicSharedMemorySize, GSMEM);
    cudaFuncSetAttribute(k_mma_gemm<2,false,true,false>, cudaFuncAttributeMaxDynamicSharedMemorySize, GSMEM);
    cudaFuncSetAttribute(k_mma_gemm<1,false,true,false>, cudaFuncAttributeMaxDynamicSharedMemorySize, GSMEM);
    cudaFuncSetAttribute(k_mma_gemm<0,true,false,true>,  cudaFuncAttributeMaxDynamicSharedMemorySize, GSMEM);
    cudaFuncSetAttribute(k_attn_tc, cudaFuncAttributeMaxDynamicSharedMemorySize, ASMEM);

    dim3 wb(32, 8);
    dim3 gD(PD / 128, NT / 128);
    dim3 gQKV(QS / 128, NT / 128);
    dim3 gF(PDFF / 128, NT / 128);

    // fused qkv weight conversion + bias + embed
    k_wconv3<<<dim3(PD/32, PD/32, 3), wb>>>(wq, wk, wv, pwqkv);
    k_bias3<<<QS / 256, 256>>>(bq, bk, bv, pbqkv);
    k_embed<<<NT, 256>>>(src, pos, tt, n1s, n1b, embs, embb, hf);
    // fused QKV GEMM -> qkv fp16 (ncu window lands here)
    k_mma_gemm<0,false,true,false><<<gQKV, 256, GSMEM>>>(hf, pwqkv, pbqkv, nullptr, nullptr, qkvf, NT, QS, PD);
    // remaining weight conversions
    k_wconv<<<dim3(PD/32,  PD/32),  wb>>>(wo,  pwo,  PD,   PD);
    k_wconv<<<dim3(PDFF/32,PD/32),  wb>>>(wi,  pwi,  PD,   PDFF);
    k_wconv<<<dim3(PD/32,  PDFF/32),wb>>>(wo2, pwo2, PDFF, PD);
    k_wconv<<<dim3(PDFF/32,PD/32),  wb>>>(w1,  pw1,  PD,   PDFF);
    k_wconv<<<dim3(PD/32,  PDFF/32),wb>>>(w2,  pw2,  PDFF, PD);
    // tensor-core banded attention (64-query blocks) -> a (fp16)
    k_attn_tc<<<dim3(PS / 64, PB * PH), 128, ASMEM>>>(qkvf, af);
    // attn out proj -> tmpf fp16
    k_mma_gemm<0,false,true,false><<<gD, 256, GSMEM>>>(af, pwo, bo, nullptr, nullptr, tmpf, NT, PD, PD);
    // h2 = ln(h + tmp)  (fp16 inputs)
    k_add_ln<<<NT, 256>>>(hf, tmpf, atts, attb, 1e-12f, h2f);
    // FFN1 + GELU -> ff (fp16)
    k_mma_gemm<2,false,true,false><<<gF, 256, GSMEM>>>(h2f, pwi, bi, nullptr, nullptr, fff, NT, PDFF, PD);
    // FFN2 -> tmpf fp16
    k_mma_gemm<0,false,true,false><<<gD, 256, GSMEM>>>(fff, pwo2, bo2, nullptr, nullptr, tmpf, NT, PD, PDFF);
    // out-LN -> src2 (fp32); n2-LN -> x (fp16)
    k_mid<<<NT, 256>>>(h2f, tmpf, outs, outb, src, n2s, n2b, p_src2, xf);
    // MLP1 + ReLU -> ff (fp16)
    k_mma_gemm<1,false,true,false><<<gF, 256, GSMEM>>>(xf, pw1, b1, nullptr, nullptr, fff, NT, PDFF, PD);
    // MLP2 + residual(src2) -> d_out (fp32)
    k_mma_gemm<0,true,false,true><<<gD, 256, GSMEM>>>(fff, pw2, b2, p_src2, out, nullptr, NT, PD, PDFF);
}

// round 17
// speedup vs baseline: 1.2832x; 1.2832x over previous
#include <cuda_runtime.h>
#include <cuda_fp16.h>
#include <math.h>
#include <stdint.h>

static constexpr int PB  = 2;
static constexpr int PS  = 8192;
static constexpr int PD  = 768;
static constexpr int PH  = 12;
static constexpr int PHD = 64;
static constexpr int PW  = 256;
static constexpr int PDFF= 3072;
static constexpr int NT  = PB * PS;     // 16384
static constexpr int QS  = 3 * PD;      // 2304 fused qkv row stride

// ---------------- scratch (device globals; no allocation) ---------------------
__device__ float g_src2[NT * PD];
__device__ float g_bqkv[QS];

// fp16 activations
__device__ __half g_hf  [NT * PD];
__device__ __half g_tmpf[NT * PD];
__device__ __half g_h2f [NT * PD];
__device__ __half g_af  [NT * PD];
__device__ __half g_xf  [NT * PD];
__device__ __half g_qkv [(size_t)NT * QS];
__device__ __half g_fff [(size_t)NT * PDFF];

// weights: fp16, TRANSPOSED to [N,K]
__device__ __half g_wqkv[QS * PD];      // rows: q(scaled 1/8), k, v
__device__ __half g_wo  [PD * PD];
__device__ __half g_wi  [PDFF * PD];
__device__ __half g_wo2 [PD * PDFF];
__device__ __half g_w1  [PDFF * PD];
__device__ __half g_w2  [PD * PDFF];

// ---------------- helpers -----------------------------------------------------
__device__ __forceinline__ uint32_t smem_u32(const void* p) {
    uint32_t a;
    asm("{ .reg .u64 t; cvta.to.shared.u64 t, %1; cvt.u32.u64 %0, t; }"
        : "=r"(a) : "l"(p));
    return a;
}
__device__ __forceinline__ void cp16(uint32_t saddr, const void* gaddr) {
    asm volatile("cp.async.cg.shared.global [%0], [%1], 16;"
                 :: "r"(saddr), "l"(gaddr) : "memory");
}
#define CP_COMMIT() asm volatile("cp.async.commit_group;" ::: "memory")
#define CP_WAIT(n)  asm volatile("cp.async.wait_group %0;" :: "n"(n) : "memory")

__device__ __forceinline__ void ldsm4(uint32_t* r, uint32_t addr) {
    asm volatile("ldmatrix.sync.aligned.m8n8.x4.shared.b16 {%0,%1,%2,%3}, [%4];"
                 : "=r"(r[0]), "=r"(r[1]), "=r"(r[2]), "=r"(r[3]) : "r"(addr));
}
__device__ __forceinline__ void ldsm4t(uint32_t* r, uint32_t addr) {
    asm volatile("ldmatrix.sync.aligned.m8n8.x4.trans.shared.b16 {%0,%1,%2,%3}, [%4];"
                 : "=r"(r[0]), "=r"(r[1]), "=r"(r[2]), "=r"(r[3]) : "r"(addr));
}
__device__ __forceinline__ void mma16816(float* c, const uint32_t* a, const uint32_t* b) {
    asm volatile(
        "mma.sync.aligned.m16n8k16.row.col.f32.f16.f16.f32 "
        "{%0,%1,%2,%3}, {%4,%5,%6,%7}, {%8,%9}, {%0,%1,%2,%3};"
        : "+f"(c[0]), "+f"(c[1]), "+f"(c[2]), "+f"(c[3])
        : "r"(a[0]), "r"(a[1]), "r"(a[2]), "r"(a[3]), "r"(b[0]), "r"(b[1]));
}
__device__ __forceinline__ uint32_t packh2(float a, float b) {
    __half2 h = __floats2half2_rn(a, b);
    return *(uint32_t*)&h;
}

// ---------------- block reduce (sum of two values, 256 threads) ---------------
__device__ __forceinline__ void reduce2(float& a, float& b, float* sbuf) {
    int lane = threadIdx.x & 31;
    int wid  = threadIdx.x >> 5;
#pragma unroll
    for (int o = 16; o > 0; o >>= 1) {
        a += __shfl_down_sync(0xffffffffu, a, o);
        b += __shfl_down_sync(0xffffffffu, b, o);
    }
    __syncthreads();
    if (lane == 0) { sbuf[wid] = a; sbuf[8 + wid] = b; }
    __syncthreads();
    if (threadIdx.x < 32) {
        a = (lane < 8) ? sbuf[lane] : 0.f;
        b = (lane < 8) ? sbuf[8 + lane] : 0.f;
#pragma unroll
        for (int o = 4; o > 0; o >>= 1) {
            a += __shfl_down_sync(0xffffffffu, a, o);
            b += __shfl_down_sync(0xffffffffu, b, o);
        }
        if (lane == 0) { sbuf[0] = a; sbuf[8] = b; }
    }
    __syncthreads();
    a = sbuf[0]; b = sbuf[8];
}

// -------- fused qkv weight convert: 3x W[768,768] -> T[2304,768], q scaled ----
__global__ void k_wconv3(const float* __restrict__ W0, const float* __restrict__ W1,
                         const float* __restrict__ W2, __half* __restrict__ Th) {
    __shared__ float t[32][33];
    int z = blockIdx.z;
    const float* W = (z == 0) ? W0 : ((z == 1) ? W1 : W2);
    float scale = (z == 0) ? 0.125f : 1.f;
    int n0 = blockIdx.x * 32, k0 = blockIdx.y * 32;
    int tx = threadIdx.x, ty = threadIdx.y;   // 32 x 8
#pragma unroll
    for (int i = 0; i < 32; i += 8)
        t[ty + i][tx] = W[(size_t)(k0 + ty + i) * PD + n0 + tx];
    __syncthreads();
#pragma unroll
    for (int i = 0; i < 32; i += 8) {
        size_t o = (size_t)(z * PD + n0 + ty + i) * PD + k0 + tx;
        Th[o] = __float2half_rn(t[tx][ty + i] * scale);
    }
}

__global__ void k_bias3(const float* __restrict__ bq, const float* __restrict__ bk,
                        const float* __restrict__ bv, float* __restrict__ o) {
    int i = blockIdx.x * 256 + threadIdx.x;
    if (i < PD) o[i] = bq[i] * 0.125f;
    else if (i < 2 * PD) o[i] = bk[i - PD];
    else if (i < QS) o[i] = bv[i - 2 * PD];
}

// -------- weight convert + transpose: W[K,N] fp32 -> T[N,K] fp16 --------------
__global__ void k_wconv(const float* __restrict__ W, __half* __restrict__ Th,
                        int K, int N) {
    __shared__ float t[32][33];
    int n0 = blockIdx.x * 32, k0 = blockIdx.y * 32;
    int tx = threadIdx.x, ty = threadIdx.y;
#pragma unroll
    for (int i = 0; i < 32; i += 8)
        t[ty + i][tx] = W[(size_t)(k0 + ty + i) * N + n0 + tx];
    __syncthreads();
#pragma unroll
    for (int i = 0; i < 32; i += 8) {
        size_t o = (size_t)(n0 + ty + i) * K + k0 + tx;
        Th[o] = __float2half_rn(t[tx][ty + i]);
    }
}

// -------- K1: double LN + pos/tt; writes h fp16 only --------------------------
__global__ void k_embed(const float* __restrict__ src, const float* __restrict__ pos,
                        const float* __restrict__ tt,
                        const float* __restrict__ n1s, const float* __restrict__ n1b,
                        const float* __restrict__ es,  const float* __restrict__ eb,
                        __half* __restrict__ oh) {
    __shared__ float sbuf[16];
    int row = blockIdx.x;
    int s   = row % PS;
    const float* x = src + (size_t)row * PD;
    int t = threadIdx.x;
    float v0 = x[t], v1 = x[t + 256], v2 = x[t + 512];
    float sum = v0 + v1 + v2, sq = v0*v0 + v1*v1 + v2*v2;
    reduce2(sum, sq, sbuf);
    float m = sum / PD;
    float r = rsqrtf(sq / PD - m * m + 1e-5f);
    const float* ps = pos + (size_t)s * PD;
    float y0 = (v0 - m) * r * n1s[t]       + n1b[t]       + ps[t]       + tt[t];
    float y1 = (v1 - m) * r * n1s[t + 256] + n1b[t + 256] + ps[t + 256] + tt[t + 256];
    float y2 = (v2 - m) * r * n1s[t + 512] + n1b[t + 512] + ps[t + 512] + tt[t + 512];
    sum = y0 + y1 + y2; sq = y0*y0 + y1*y1 + y2*y2;
    reduce2(sum, sq, sbuf);
    m = sum / PD;
    r = rsqrtf(sq / PD - m * m + 1e-12f);
    size_t base = (size_t)row * PD;
    oh[base + t]       = __float2half_rn((y0 - m) * r * es[t]       + eb[t]);
    oh[base + t + 256] = __float2half_rn((y1 - m) * r * es[t + 256] + eb[t + 256]);
    oh[base + t + 512] = __float2half_rn((y2 - m) * r * es[t + 512] + eb[t + 512]);
}

// -------- out = ln(a + b) with fp16 inputs; writes fp16 -----------------------
__global__ void k_add_ln(const __half* __restrict__ a, const __half* __restrict__ b,
                         const float* __restrict__ sc, const float* __restrict__ bv,
                         float eps, __half* __restrict__ oh) {
    __shared__ float sbuf[16];
    int row = blockIdx.x;
    int t = threadIdx.x;
    size_t base = (size_t)row * PD;
    float y0 = __half2float(a[base + t])       + __half2float(b[base + t]);
    float y1 = __half2float(a[base + t + 256]) + __half2float(b[base + t + 256]);
    float y2 = __half2float(a[base + t + 512]) + __half2float(b[base + t + 512]);
    float sum = y0 + y1 + y2, sq = y0*y0 + y1*y1 + y2*y2;
    reduce2(sum, sq, sbuf);
    float m = sum / PD;
    float r = rsqrtf(sq / PD - m * m + eps);
    oh[base + t]       = __float2half_rn((y0 - m) * r * sc[t]       + bv[t]);
    oh[base + t + 256] = __float2half_rn((y1 - m) * r * sc[t + 256] + bv[t + 256]);
    oh[base + t + 512] = __float2half_rn((y2 - m) * r * sc[t + 512] + bv[t + 512]);
}

// -------- out-LN -> src2 (fp32) -> n2-LN -> x (fp16); fp16 inputs -------------
__global__ void k_mid(const __half* __restrict__ h2, const __half* __restrict__ tp,
                      const float* __restrict__ os, const float* __restrict__ ob,
                      const float* __restrict__ src,
                      const float* __restrict__ n2s, const float* __restrict__ n2b,
                      float* __restrict__ src2, __half* __restrict__ xh) {
    __shared__ float sbuf[16];
    int row = blockIdx.x;
    int t = threadIdx.x;
    size_t base = (size_t)row * PD;
    float y0 = __half2float(h2[base + t])       + __half2float(tp[base + t]);
    float y1 = __half2float(h2[base + t + 256]) + __half2float(tp[base + t + 256]);
    float y2 = __half2float(h2[base + t + 512]) + __half2float(tp[base + t + 512]);
    float sum = y0 + y1 + y2, sq = y0*y0 + y1*y1 + y2*y2;
    reduce2(sum, sq, sbuf);
    float m = sum / PD;
    float r = rsqrtf(sq / PD - m * m + 1e-12f);
    const float* sp = src + base;
    float s0 = sp[t]       + (y0 - m) * r * os[t]       + ob[t];
    float s1 = sp[t + 256] + (y1 - m) * r * os[t + 256] + ob[t + 256];
    float s2 = sp[t + 512] + (y2 - m) * r * os[t + 512] + ob[t + 512];
    src2[base + t] = s0; src2[base + t + 256] = s1; src2[base + t + 512] = s2;
    sum = s0 + s1 + s2; sq = s0*s0 + s1*s1 + s2*s2;
    reduce2(sum, sq, sbuf);
    m = sum / PD;
    r = rsqrtf(sq / PD - m * m + 1e-5f);
    xh[base + t]       = __float2half_rn((s0 - m) * r * n2s[t]       + n2b[t]);
    xh[base + t + 256] = __float2half_rn((s1 - m) * r * n2s[t + 256] + n2b[t + 256]);
    xh[base + t + 512] = __float2half_rn((s2 - m) * r * n2s[t + 512] + n2b[t + 512]);
}

// ---------------- HMMA GEMM: C = act(A@B^T + bias) (+res) ---------------------
static constexpr int LDT   = 72;
static constexpr int ABYTES= 128 * LDT * 2;     // 18432 per array
static constexpr int STAGE = 2 * ABYTES;        // 36864 (A, B)
static constexpr int NSTG  = 3;
static constexpr int GSMEM = NSTG * STAGE;      // 110592

template<int MODE, bool WF32, bool WH, bool HASRES>
__global__ void __launch_bounds__(128, 2)
k_mma_gemm(const __half* __restrict__ A, const __half* __restrict__ B,
           const float* __restrict__ bias, const float* __restrict__ res,
           float* __restrict__ Cf, __half* __restrict__ Chh,
           int M, int N, int K) {
    extern __shared__ char smem[];
    uint32_t sbase = smem_u32(smem);
    int tid  = threadIdx.x;
    int wid  = tid >> 5, lane = tid & 31;
    int wm   = (wid >> 1) * 64;
    int wn   = (wid & 1) * 64;

    int m0 = blockIdx.y * 128, n0 = blockIdx.x * 128;
    int nK = K >> 6;

    const __half* pa = A + (size_t)m0 * K;
    const __half* pb = B + (size_t)n0 * K;

    float acc[4][8][4];
#pragma unroll
    for (int a = 0; a < 4; a++)
#pragma unroll
        for (int b = 0; b < 8; b++)
#pragma unroll
            for (int c = 0; c < 4; c++) acc[a][b][c] = 0.f;

    int lrow = tid >> 3;
    int lseg = tid & 7;

    auto load_stage = [&](int kc, int s) {
        uint32_t st = sbase + s * STAGE;
        size_t ko = (size_t)(kc << 6) + (size_t)lseg * 8;
#pragma unroll
        for (int i = 0; i < 8; i++) {
            int r = lrow + i * 16;
            uint32_t so = (uint32_t)r * (LDT * 2) + (uint32_t)lseg * 16;
            size_t go = (size_t)r * K + ko;
            cp16(st + so,          pa + go);
            cp16(st + ABYTES + so, pb + go);
        }
    };

    load_stage(0, 0); CP_COMMIT();
    load_stage(1, 1); CP_COMMIT();

    int a_r  = lane & 15;
    int a_k8 = (lane >> 4) * 8;
    int b4_r = ((lane >> 4) & 1) * 8 + (lane & 7);
    int b4_k8= ((lane >> 3) & 1) * 8;

    for (int kc = 0; kc < nK; kc++) {
        int s = kc % NSTG;
        if (kc + 1 < nK) { CP_WAIT(1); } else { CP_WAIT(0); }
        __syncthreads();
        if (kc + 2 < nK) { load_stage(kc + 2, (kc + 2) % NSTG); CP_COMMIT(); }

        uint32_t sA = sbase + s * STAGE;
        uint32_t sB = sA + ABYTES;
#pragma unroll
        for (int ks = 0; ks < 4; ks++) {
            uint32_t ah[4][4], bf[4][4];
#pragma unroll
            for (int mi = 0; mi < 4; mi++) {
                uint32_t off = ((uint32_t)(wm + mi * 16 + a_r) * LDT +
                                (uint32_t)(ks * 16 + a_k8)) * 2;
                ldsm4(ah[mi], sA + off);
            }
#pragma unroll
            for (int p = 0; p < 4; p++) {
                uint32_t off = ((uint32_t)(wn + p * 16 + b4_r) * LDT +
                                (uint32_t)(ks * 16 + b4_k8)) * 2;
                ldsm4(bf[p], sB + off);
            }
#pragma unroll
            for (int mi = 0; mi < 4; mi++)
#pragma unroll
                for (int p = 0; p < 4; p++) {
                    mma16816(acc[mi][2 * p],     ah[mi], &bf[p][0]);
                    mma16816(acc[mi][2 * p + 1], ah[mi], &bf[p][2]);
                }
        }
        __syncthreads();
    }

    auto epi = [&](float v0, float v1, int m, int n) {
        float2 bb = *(const float2*)(bias + n);
        float o0 = v0 + bb.x;
        float o1 = v1 + bb.y;
        if (MODE == 1) { o0 = fmaxf(o0, 0.f); o1 = fmaxf(o1, 0.f); }
        if (MODE == 2) {
            o0 = 0.5f * o0 * (1.f + erff(o0 * 0.7071067811865476f));
            o1 = 0.5f * o1 * (1.f + erff(o1 * 0.7071067811865476f));
        }
        size_t off = (size_t)m * N + n;
        if (HASRES) {
            float2 rr = *(const float2*)(res + off);
            o0 += rr.x; o1 += rr.y;
        }
        if (WF32) {
            float2 ov = { o0, o1 };
            *(float2*)(Cf + off) = ov;
        }
        if (WH) {
            __half2 hv; hv.x = __float2half_rn(o0); hv.y = __float2half_rn(o1);
            *(__half2*)(Chh + off) = hv;
        }
    };
    int mrow = lane >> 2;
    int ncol = (lane & 3) * 2;
#pragma unroll
    for (int mi = 0; mi < 4; mi++)
#pragma unroll
        for (int ni = 0; ni < 8; ni++) {
            int m = m0 + wm + mi * 16 + mrow;
            int n = n0 + wn + ni * 8 + ncol;
            epi(acc[mi][ni][0], acc[mi][ni][1], m,     n);
            epi(acc[mi][ni][2], acc[mi][ni][3], m + 8, n);
        }
}

// ---------------- tensor-core banded flash attention (64-query blocks) --------
static constexpr int LDA   = 72;                // halves
static constexpr int ATILE = 64 * LDA;          // halves per tile
static constexpr int ASMEM = (5 * ATILE) * 2;   // Q + 2 stages * (K,V) = 46080 B

__global__ void __launch_bounds__(128)
k_attn_tc(const __half* __restrict__ QKV, __half* __restrict__ Og) {
    extern __shared__ __half sa[];
    uint32_t sbQ  = smem_u32(sa);
    uint32_t sbKV = sbQ + ATILE * 2;

    int tid = threadIdx.x, wid = tid >> 5, lane = tid & 31;
    int wm = wid * 16;
    int qc = blockIdx.x, bh = blockIdx.y;
    int b = bh / PH, hh = bh % PH;
    int qbase = qc * 64;
    size_t tokq = (size_t)b * PS + qbase;
    const __half* qsrc = QKV + tokq * QS + hh * PHD;

#pragma unroll
    for (int i = 0; i < 4; i++) {
        int idx = tid + i * 128;
        int row = idx >> 3, seg = idx & 7;
        cp16(sbQ + (uint32_t)(row * LDA + seg * 8) * 2,
             qsrc + (size_t)row * QS + seg * 8);
    }

    int t0 = qbase >= 256 ? 0 : (256 - qbase) / 64;
    int t1 = (PS + 192 - qbase) / 64; if (t1 > 8) t1 = 8;

    auto stage_kv = [&](int t, int s) {
        int tb = qbase - 256 + t * 64;
        size_t tok = (size_t)b * PS + tb;
        const __half* ks = QKV + tok * QS + PD + hh * PHD;
        const __half* vs = QKV + tok * QS + 2 * PD + hh * PHD;
        uint32_t dstK = sbKV + (uint32_t)(s * 2 * ATILE) * 2;
        uint32_t dstV = dstK + ATILE * 2;
#pragma unroll
        for (int i = 0; i < 4; i++) {
            int idx = tid + i * 128;
            int row = idx >> 3, seg = idx & 7;
            uint32_t so = (uint32_t)(row * LDA + seg * 8) * 2;
            size_t go = (size_t)row * QS + seg * 8;
            cp16(dstK + so, ks + go);
            cp16(dstV + so, vs + go);
        }
    };

    stage_kv(t0, 0);
    CP_COMMIT();

    uint32_t qf[4][4];
    float O[8][4];
#pragma unroll
    for (int i = 0; i < 8; i++)
#pragma unroll
        for (int j = 0; j < 4; j++) O[i][j] = 0.f;
    float m0 = -1e30f, m1 = -1e30f, l0 = 0.f, l1 = 0.f;

    int a_r = lane & 15, a_k8 = (lane >> 4) * 8;
    int kn_r = (lane >> 4) * 8 + (lane & 7);
    int kn_c = ((lane >> 3) & 1) * 8;
    int v_r  = ((lane >> 3) & 1) * 8 + (lane & 7);
    int v_c  = (lane >> 4) * 8;

    for (int t = t0; t <= t1; t++) {
        int s = (t - t0) & 1;
        if (t < t1) { stage_kv(t + 1, s ^ 1); CP_COMMIT(); CP_WAIT(1); }
        else CP_WAIT(0);
        __syncthreads();
        if (t == t0) {
#pragma unroll
            for (int kk = 0; kk < 4; kk++)
                ldsm4(qf[kk], sbQ + (uint32_t)((wm + a_r) * LDA + kk * 16 + a_k8) * 2);
        }
        uint32_t sK = sbKV + (uint32_t)(s * 2 * ATILE) * 2;
        uint32_t sV = sK + ATILE * 2;

        float S[8][4];
#pragma unroll
        for (int i = 0; i < 8; i++)
#pragma unroll
            for (int j = 0; j < 4; j++) S[i][j] = 0.f;
#pragma unroll
        for (int np = 0; np < 4; np++) {
#pragma unroll
            for (int kk = 0; kk < 4; kk++) {
                uint32_t kf[4];
                ldsm4(kf, sK + (uint32_t)((np * 16 + kn_r) * LDA + kk * 16 + kn_c) * 2);
                mma16816(S[2 * np],     qf[kk], kf);
                mma16816(S[2 * np + 1], qf[kk], kf + 2);
            }
        }

        if (t == 0) {
            int i0 = wm + (lane >> 2);
#pragma unroll
            for (int ni = 0; ni < 8; ni++) {
                int j0 = ni * 8 + (lane & 3) * 2;
                if (j0     < i0)     S[ni][0] = -1e30f;
                if (j0 + 1 < i0)     S[ni][1] = -1e30f;
                if (j0     < i0 + 8) S[ni][2] = -1e30f;
                if (j0 + 1 < i0 + 8) S[ni][3] = -1e30f;
            }
        } else if (t == 8) {
            int i0 = wm + (lane >> 2);
#pragma unroll
            for (int ni = 0; ni < 8; ni++) {
                int j0 = ni * 8 + (lane & 3) * 2;
                if (j0     > i0)     S[ni][0] = -1e30f;
                if (j0 + 1 > i0)     S[ni][1] = -1e30f;
                if (j0     > i0 + 8) S[ni][2] = -1e30f;
                if (j0 + 1 > i0 + 8) S[ni][3] = -1e30f;
            }
        }

        float mx0 = -1e30f, mx1 = -1e30f;
#pragma unroll
        for (int ni = 0; ni < 8; ni++) {
            mx0 = fmaxf(mx0, fmaxf(S[ni][0], S[ni][1]));
            mx1 = fmaxf(mx1, fmaxf(S[ni][2], S[ni][3]));
        }
        mx0 = fmaxf(mx0, __shfl_xor_sync(0xffffffffu, mx0, 1));
        mx0 = fmaxf(mx0, __shfl_xor_sync(0xffffffffu, mx0, 2));
        mx1 = fmaxf(mx1, __shfl_xor_sync(0xffffffffu, mx1, 1));
        mx1 = fmaxf(mx1, __shfl_xor_sync(0xffffffffu, mx1, 2));
        float mn0 = fmaxf(m0, mx0), mn1 = fmaxf(m1, mx1);
        float c0 = __expf(m0 - mn0), c1 = __expf(m1 - mn1);
        float rs0 = 0.f, rs1 = 0.f;
#pragma unroll
        for (int ni = 0; ni < 8; ni++) {
            S[ni][0] = __expf(S[ni][0] - mn0);
            S[ni][1] = __expf(S[ni][1] - mn0);
            S[ni][2] = __expf(S[ni][2] - mn1);
            S[ni][3] = __expf(S[ni][3] - mn1);
            rs0 += S[ni][0] + S[ni][1];
            rs1 += S[ni][2] + S[ni][3];
        }
        rs0 += __shfl_xor_sync(0xffffffffu, rs0, 1);
        rs0 += __shfl_xor_sync(0xffffffffu, rs0, 2);
        rs1 += __shfl_xor_sync(0xffffffffu, rs1, 1);
        rs1 += __shfl_xor_sync(0xffffffffu, rs1, 2);
        l0 = l0 * c0 + rs0;
        l1 = l1 * c1 + rs1;
        m0 = mn0; m1 = mn1;
#pragma unroll
        for (int ni = 0; ni < 8; ni++) {
            O[ni][0] *= c0; O[ni][1] *= c0;
            O[ni][2] *= c1; O[ni][3] *= c1;
        }

        uint32_t ap[4][4];
#pragma unroll
        for (int kk = 0; kk < 4; kk++) {
            ap[kk][0] = packh2(S[2 * kk][0],     S[2 * kk][1]);
            ap[kk][1] = packh2(S[2 * kk][2],     S[2 * kk][3]);
            ap[kk][2] = packh2(S[2 * kk + 1][0], S[2 * kk + 1][1]);
            ap[kk][3] = packh2(S[2 * kk + 1][2], S[2 * kk + 1][3]);
        }
#pragma unroll
        for (int np = 0; np < 4; np++) {
#pragma unroll
            for (int kk = 0; kk < 4; kk++) {
                uint32_t vf[4];
                ldsm4t(vf, sV + (uint32_t)((kk * 16 + v_r) * LDA + np * 16 + v_c) * 2);
                mma16816(O[2 * np],     ap[kk], vf);
                mma16816(O[2 * np + 1], ap[kk], vf + 2);
            }
        }
        __syncthreads();
    }

    float inv0 = 1.f / l0, inv1 = 1.f / l1;
    int i0 = wm + (lane >> 2);
    size_t rb0 = (tokq + i0) * PD + hh * PHD;
    size_t rb1 = (tokq + i0 + 8) * PD + hh * PHD;
#pragma unroll
    for (int ni = 0; ni < 8; ni++) {
        int j0 = ni * 8 + (lane & 3) * 2;
        __half2 h0 = __floats2half2_rn(O[ni][0] * inv0, O[ni][1] * inv0);
        __half2 h1 = __floats2half2_rn(O[ni][2] * inv1, O[ni][3] * inv1);
        *(__half2*)(Og + rb0 + j0) = h0;
        *(__half2*)(Og + rb1 + j0) = h1;
    }
}

// ------------------------------- launch ---------------------------------------
extern "C" void kernel_launch(void* const* d_in, const int* in_sizes, int n_in,
                              void* d_out, int out_size) {
    const float* src   = (const float*)d_in[0];
    const float* pos   = (const float*)d_in[1];
    const float* tt    = (const float*)d_in[2];
    const float* embs  = (const float*)d_in[3];
    const float* embb  = (const float*)d_in[4];
    const float* wq    = (const float*)d_in[5];
    const float* bq    = (const float*)d_in[6];
    const float* wk    = (const float*)d_in[7];
    const float* bk    = (const float*)d_in[8];
    const float* wv    = (const float*)d_in[9];
    const float* bv    = (const float*)d_in[10];
    const float* wo    = (const float*)d_in[11];
    const float* bo    = (const float*)d_in[12];
    const float* atts  = (const float*)d_in[13];
    const float* attb  = (const float*)d_in[14];
    const float* wi    = (const float*)d_in[15];
    const float* bi    = (const float*)d_in[16];
    const float* wo2   = (const float*)d_in[17];
    const float* bo2   = (const float*)d_in[18];
    const float* outs  = (const float*)d_in[19];
    const float* outb  = (const float*)d_in[20];
    const float* n1s   = (const float*)d_in[21];
    const float* n1b   = (const float*)d_in[22];
    const float* n2s   = (const float*)d_in[23];
    const float* n2b   = (const float*)d_in[24];
    const float* w1    = (const float*)d_in[25];
    const float* b1    = (const float*)d_in[26];
    const float* w2    = (const float*)d_in[27];
    const float* b2    = (const float*)d_in[28];
    float* out = (float*)d_out;

    float *p_src2, *pbqkv;
    cudaGetSymbolAddress((void**)&p_src2, g_src2);
    cudaGetSymbolAddress((void**)&pbqkv,  g_bqkv);

    __half *hf, *tmpf, *h2f, *af, *xf, *fff, *qkvf;
    cudaGetSymbolAddress((void**)&hf,   g_hf);
    cudaGetSymbolAddress((void**)&tmpf, g_tmpf);
    cudaGetSymbolAddress((void**)&h2f,  g_h2f);
    cudaGetSymbolAddress((void**)&af,   g_af);
    cudaGetSymbolAddress((void**)&xf,   g_xf);
    cudaGetSymbolAddress((void**)&fff,  g_fff);
    cudaGetSymbolAddress((void**)&qkvf, g_qkv);

    __half *pwqkv, *pwo, *pwi, *pwo2, *pw1, *pw2;
    cudaGetSymbolAddress((void**)&pwqkv, g_wqkv);
    cudaGetSymbolAddress((void**)&pwo,   g_wo);
    cudaGetSymbolAddress((void**)&pwi,   g_wi);
    cudaGetSymbolAddress((void**)&pwo2,  g_wo2);
    cudaGetSymbolAddress((void**)&pw1,   g_w1);
    cudaGetSymbolAddress((void**)&pw2,   g_w2);

    cudaFuncSetAttribute(k_mma_gemm<0,false,true,false>, cudaFuncAttributeMaxDynamicSharedMemorySize, GSMEM);
    cudaFuncSetAttribute(k_mma_gemm<2,false,true,false>, cudaFuncAttributeMaxDynamicSharedMemorySize, GSMEM);
    cudaFuncSetAttribute(k_mma_gemm<1,false,true,false>, cudaFuncAttributeMaxDynamicSharedMemorySize, GSMEM);
    cudaFuncSetAttribute(k_mma_gemm<0,true,false,true>,  cudaFuncAttributeMaxDynamicSharedMemorySize, GSMEM);
    cudaFuncSetAttribute(k_attn_tc, cudaFuncAttributeMaxDynamicSharedMemorySize, ASMEM);

    dim3 wb(32, 8);
    dim3 gD(PD / 128, NT / 128);
    dim3 gQKV(QS / 128, NT / 128);
    dim3 gF(PDFF / 128, NT / 128);

    // fused qkv weight conversion + bias + embed
    k_wconv3<<<dim3(PD/32, PD/32, 3), wb>>>(wq, wk, wv, pwqkv);
    k_bias3<<<QS / 256, 256>>>(bq, bk, bv, pbqkv);
    k_embed<<<NT, 256>>>(src, pos, tt, n1s, n1b, embs, embb, hf);
    // fused QKV GEMM -> qkv fp16
    k_mma_gemm<0,false,true,false><<<gQKV, 128, GSMEM>>>(hf, pwqkv, pbqkv, nullptr, nullptr, qkvf, NT, QS, PD);
    // remaining weight conversions
    k_wconv<<<dim3(PD/32,  PD/32),  wb>>>(wo,  pwo,  PD,   PD);
    k_wconv<<<dim3(PDFF/32,PD/32),  wb>>>(wi,  pwi,  PD,   PDFF);
    k_wconv<<<dim3(PD/32,  PDFF/32),wb>>>(wo2, pwo2, PDFF, PD);
    k_wconv<<<dim3(PDFF/32,PD/32),  wb>>>(w1,  pw1,  PD,   PDFF);
    k_wconv<<<dim3(PD/32,  PDFF/32),wb>>>(w2,  pw2,  PDFF, PD);
    // tensor-core banded attention (64-query blocks) -> a (fp16)
    k_attn_tc<<<dim3(PS / 64, PB * PH), 128, ASMEM>>>(qkvf, af);
    // attn out proj -> tmpf fp16
    k_mma_gemm<0,false,true,false><<<gD, 128, GSMEM>>>(af, pwo, bo, nullptr, nullptr, tmpf, NT, PD, PD);
    // h2 = ln(h + tmp)  (fp16 inputs)
    k_add_ln<<<NT, 256>>>(hf, tmpf, atts, attb, 1e-12f, h2f);
    // FFN1 + GELU -> ff (fp16)
    k_mma_gemm<2,false,true,false><<<gF, 128, GSMEM>>>(h2f, pwi, bi, nullptr, nullptr, fff, NT, PDFF, PD);
    // FFN2 -> tmpf fp16
    k_mma_gemm<0,false,true,false><<<gD, 128, GSMEM>>>(fff, pwo2, bo2, nullptr, nullptr, tmpf, NT, PD, PDFF);
    // out-LN -> src2 (fp32); n2-LN -> x (fp16)
    k_mid<<<NT, 256>>>(h2f, tmpf, outs, outb, src, n2s, n2b, p_src2, xf);
    // MLP1 + ReLU -> ff (fp16)
    k_mma_gemm<1,false,true,false><<<gF, 128, GSMEM>>>(xf, pw1, b1, nullptr, nullptr, fff, NT, PDFF, PD);
    // MLP2 + residual(src2) -> d_out (fp32)
    k_mma_gemm<0,true,false,true><<<gD, 128, GSMEM>>>(fff, pw2, b2, p_src2, out, nullptr, NT, PD, PDFF);
}